// round 1
// baseline (speedup 1.0000x reference)
#include <cuda_runtime.h>
#include <math.h>

#define NNODES 50000
#define NEDGES 1600000
#define ETOT   (NEDGES + NNODES)
#define INCH   64
#define HEADS  8
#define HID    16
#define HH     (HEADS*HID)   /* 128 */
#define NGRAPH 256
#define OUTC   32

// ---------------- scratch (static device arrays; allocation-free) ----------------
__device__ __align__(16) float g_xl1[NNODES*HH];
__device__ __align__(16) float g_xr1[NNODES*HH];
__device__ __align__(16) float g_a1[(size_t)ETOT*HEADS];
__device__ __align__(16) float g_denom1[NNODES*HEADS];
__device__ __align__(16) float g_out1[NNODES*HH];
__device__ __align__(16) float g_xl2[NNODES*HID];
__device__ __align__(16) float g_xr2[NNODES*HID];
__device__ __align__(16) float g_a2[ETOT];
__device__ __align__(16) float g_denom2[NNODES];
__device__ __align__(16) float g_out2[NNODES*HID];
__device__ __align__(16) float g_pool[NGRAPH*HID];
__device__ __align__(16) float g_cnt[NGRAPH];

// ---------------- helpers ----------------
__device__ __forceinline__ void red_add_v4(float* p, float4 v) {
    unsigned long long gp = (unsigned long long)__cvta_generic_to_global((void*)p);
    asm volatile("red.global.add.v4.f32 [%0], {%1,%2,%3,%4};"
                 :: "l"(gp), "f"(v.x), "f"(v.y), "f"(v.z), "f"(v.w) : "memory");
}

__device__ __forceinline__ float elu1f(float v) {
    return v > 0.f ? v : expm1f(v);
}

// ---------------- zero accumulators ----------------
__global__ void zero_kernel() {
    int stride = gridDim.x * blockDim.x;
    int i0 = blockIdx.x * blockDim.x + threadIdx.x;
    for (int i = i0; i < NNODES*HH;    i += stride) g_out1[i]   = 0.f;
    for (int i = i0; i < NNODES*HEADS; i += stride) g_denom1[i] = 0.f;
    for (int i = i0; i < NNODES*HID;   i += stride) g_out2[i]   = 0.f;
    for (int i = i0; i < NNODES;       i += stride) g_denom2[i] = 0.f;
    for (int i = i0; i < NGRAPH*HID;   i += stride) g_pool[i]   = 0.f;
    for (int i = i0; i < NGRAPH;       i += stride) g_cnt[i]    = 0.f;
}

// ---------------- conv1 node transforms: xl1 = x@wl1+bl1, xr1 = x@wr1+br1 ----------------
__global__ void gemm1_kernel(const float* __restrict__ x,
                             const float* __restrict__ wl, const float* __restrict__ bl,
                             const float* __restrict__ wr, const float* __restrict__ br) {
    __shared__ float xs[8][INCH];
    int tid = threadIdx.x;                 // 256 threads: 0..127 -> wl cols, 128..255 -> wr cols
    int c = tid & (HH - 1);
    const float* w = (tid < HH) ? wl : wr;
    float bias = (tid < HH) ? bl[c] : br[c];
    int node0 = blockIdx.x * 32;
    for (int base = 0; base < 32; base += 8) {
        int n0 = node0 + base;
        __syncthreads();
        for (int i = tid; i < 8 * INCH; i += 256) {
            int nn = i >> 6, kk = i & 63;
            int g = n0 + nn;
            xs[nn][kk] = (g < NNODES) ? x[g * INCH + kk] : 0.f;
        }
        __syncthreads();
        float acc[8];
        #pragma unroll
        for (int j = 0; j < 8; j++) acc[j] = bias;
        #pragma unroll 8
        for (int k = 0; k < INCH; k++) {
            float wv = __ldg(&w[k * HH + c]);
            #pragma unroll
            for (int j = 0; j < 8; j++) acc[j] += xs[j][k] * wv;
        }
        float* outp = (tid < HH) ? g_xl1 : g_xr1;
        #pragma unroll
        for (int j = 0; j < 8; j++) {
            int g = n0 + j;
            if (g < NNODES) outp[(size_t)g * HH + c] = acc[j];
        }
    }
}

// ---------------- conv1 edge pass A: logits -> exp -> denom ----------------
__global__ void edge1_logit_kernel(const int* __restrict__ src, const int* __restrict__ dst,
                                   const float* __restrict__ att) {
    int gid = blockIdx.x * blockDim.x + threadIdx.x;
    if (gid >= ETOT * HEADS) return;
    int e = gid >> 3, h = gid & 7;
    int s, d;
    if (e < NEDGES) { s = src[e]; d = dst[e]; } else { s = e - NEDGES; d = s; }
    const float4* pl = (const float4*)(g_xl1 + (size_t)s * HH + h * HID);
    const float4* pr = (const float4*)(g_xr1 + (size_t)d * HH + h * HID);
    const float4* pa = (const float4*)(att + h * HID);
    float acc = 0.f;
    #pragma unroll
    for (int j = 0; j < 4; j++) {
        float4 a = pl[j], b = pr[j], w = __ldg(&pa[j]);
        float v;
        v = a.x + b.x; v = v > 0.f ? v : 0.2f * v; acc += v * w.x;
        v = a.y + b.y; v = v > 0.f ? v : 0.2f * v; acc += v * w.y;
        v = a.z + b.z; v = v > 0.f ? v : 0.2f * v; acc += v * w.z;
        v = a.w + b.w; v = v > 0.f ? v : 0.2f * v; acc += v * w.w;
    }
    float ex = __expf(acc);   // logits are O(1); max-shift unnecessary for fp32
    g_a1[gid] = ex;
    atomicAdd(&g_denom1[d * HEADS + h], ex);
}

// ---------------- conv1 edge pass B: alpha-weighted message scatter ----------------
__global__ void edge1_scatter_kernel(const int* __restrict__ src, const int* __restrict__ dst) {
    int gid = blockIdx.x * blockDim.x + threadIdx.x;
    if (gid >= ETOT * HEADS) return;
    int e = gid >> 3, h = gid & 7;
    int s, d;
    if (e < NEDGES) { s = src[e]; d = dst[e]; } else { s = e - NEDGES; d = s; }
    float a = g_a1[gid];
    float alpha = a / (g_denom1[d * HEADS + h] + 1e-16f);
    const float4* pl = (const float4*)(g_xl1 + (size_t)s * HH + h * HID);
    float* po = g_out1 + (size_t)d * HH + h * HID;
    #pragma unroll
    for (int j = 0; j < 4; j++) {
        float4 v = pl[j];
        v.x *= alpha; v.y *= alpha; v.z *= alpha; v.w *= alpha;
        red_add_v4(po + 4 * j, v);
    }
}

// ---------------- ELU after conv1 (+bias), in place ----------------
__global__ void elu1_kernel(const float* __restrict__ bias) {
    int i = blockIdx.x * blockDim.x + threadIdx.x;
    if (i < NNODES * HH) {
        float v = g_out1[i] + bias[i & (HH - 1)];
        g_out1[i] = elu1f(v);
    }
}

// ---------------- conv2 node transforms: xl2 = h1@wl2+bl2, xr2 = h1@wr2+br2 ----------------
__global__ void gemm2_kernel(const float* __restrict__ wl, const float* __restrict__ bl,
                             const float* __restrict__ wr, const float* __restrict__ br) {
    __shared__ float ws[HH][32];
    __shared__ float bs[32];
    __shared__ float xs[8][HH];
    int tid = threadIdx.x;     // 256
    for (int i = tid; i < HH * 32; i += 256) {
        int k = i >> 5, cc = i & 31;
        ws[k][cc] = (cc < HID) ? wl[k * HID + cc] : wr[k * HID + (cc - HID)];
    }
    if (tid < 32) bs[tid] = (tid < HID) ? bl[tid] : br[tid - HID];
    int col = tid & 31;
    int ln = tid >> 5;
    int node0 = blockIdx.x * 32;
    for (int base = 0; base < 32; base += 8) {
        int n0 = node0 + base;
        __syncthreads();
        for (int i = tid; i < 8 * HH; i += 256) {
            int nn = i >> 7, kk = i & 127;
            int g = n0 + nn;
            xs[nn][kk] = (g < NNODES) ? g_out1[(size_t)g * HH + kk] : 0.f;
        }
        __syncthreads();
        int g = n0 + ln;
        float acc = bs[col];
        #pragma unroll 8
        for (int k = 0; k < HH; k++) acc += xs[ln][k] * ws[k][col];
        if (g < NNODES) {
            if (col < HID) g_xl2[(size_t)g * HID + col] = acc;
            else           g_xr2[(size_t)g * HID + (col - HID)] = acc;
        }
    }
}

// ---------------- conv2 edge pass A ----------------
__global__ void edge2_logit_kernel(const int* __restrict__ src, const int* __restrict__ dst,
                                   const float* __restrict__ att) {
    int e = blockIdx.x * blockDim.x + threadIdx.x;
    if (e >= ETOT) return;
    int s, d;
    if (e < NEDGES) { s = src[e]; d = dst[e]; } else { s = e - NEDGES; d = s; }
    const float4* pl = (const float4*)(g_xl2 + (size_t)s * HID);
    const float4* pr = (const float4*)(g_xr2 + (size_t)d * HID);
    const float4* pa = (const float4*)att;
    float acc = 0.f;
    #pragma unroll
    for (int j = 0; j < 4; j++) {
        float4 a = pl[j], b = pr[j], w = __ldg(&pa[j]);
        float v;
        v = a.x + b.x; v = v > 0.f ? v : 0.2f * v; acc += v * w.x;
        v = a.y + b.y; v = v > 0.f ? v : 0.2f * v; acc += v * w.y;
        v = a.z + b.z; v = v > 0.f ? v : 0.2f * v; acc += v * w.z;
        v = a.w + b.w; v = v > 0.f ? v : 0.2f * v; acc += v * w.w;
    }
    float ex = __expf(acc);
    g_a2[e] = ex;
    atomicAdd(&g_denom2[d], ex);
}

// ---------------- conv2 edge pass B ----------------
__global__ void edge2_scatter_kernel(const int* __restrict__ src, const int* __restrict__ dst) {
    int e = blockIdx.x * blockDim.x + threadIdx.x;
    if (e >= ETOT) return;
    int s, d;
    if (e < NEDGES) { s = src[e]; d = dst[e]; } else { s = e - NEDGES; d = s; }
    float alpha = g_a2[e] / (g_denom2[d] + 1e-16f);
    const float4* pl = (const float4*)(g_xl2 + (size_t)s * HID);
    float* po = g_out2 + (size_t)d * HID;
    #pragma unroll
    for (int j = 0; j < 4; j++) {
        float4 v = pl[j];
        v.x *= alpha; v.y *= alpha; v.z *= alpha; v.w *= alpha;
        red_add_v4(po + 4 * j, v);
    }
}

// ---------------- ELU(conv2 + bias2) + global mean pool (sum + count) ----------------
__global__ void pool_kernel(const int* __restrict__ batch, const float* __restrict__ bias) {
    int n = blockIdx.x * blockDim.x + threadIdx.x;
    if (n >= NNODES) return;
    int b = batch[n];
    const float4* ph = (const float4*)(g_out2 + (size_t)n * HID);
    float* pp = g_pool + b * HID;
    #pragma unroll
    for (int j = 0; j < 4; j++) {
        float4 v = ph[j];
        float4 o;
        o.x = elu1f(v.x + bias[4 * j + 0]);
        o.y = elu1f(v.y + bias[4 * j + 1]);
        o.z = elu1f(v.z + bias[4 * j + 2]);
        o.w = elu1f(v.w + bias[4 * j + 3]);
        red_add_v4(pp + 4 * j, o);
    }
    atomicAdd(&g_cnt[b], 1.f);
}

// ---------------- final MLP on [256,16] -> [256,32] ----------------
__global__ void mlp_kernel(const float* __restrict__ w1, const float* __restrict__ b1,
                           const float* __restrict__ w2, const float* __restrict__ b2,
                           const float* __restrict__ w3, const float* __restrict__ b3,
                           float* __restrict__ out) {
    __shared__ float s1[HID * 32], sb1[32];
    __shared__ float s2[32 * HID], sb2[HID];
    __shared__ float s3[HID * 32], sb3[32];
    int tid = threadIdx.x;    // 256 threads = 256 graphs
    for (int i = tid; i < HID * 32; i += 256) s1[i] = w1[i];
    for (int i = tid; i < 32 * HID; i += 256) s2[i] = w2[i];
    for (int i = tid; i < HID * 32; i += 256) s3[i] = w3[i];
    if (tid < 32) { sb1[tid] = b1[tid]; sb3[tid] = b3[tid]; }
    if (tid < HID) sb2[tid] = b2[tid];
    __syncthreads();
    int b = tid;
    float cnt = fmaxf(g_cnt[b], 1.f);
    float h[HID];
    #pragma unroll
    for (int c = 0; c < HID; c++) h[c] = g_pool[b * HID + c] / cnt;
    float t1[32];
    #pragma unroll
    for (int j = 0; j < 32; j++) {
        float s = sb1[j];
        #pragma unroll
        for (int k = 0; k < HID; k++) s += h[k] * s1[k * 32 + j];
        t1[j] = elu1f(s);
    }
    float t2[HID];
    #pragma unroll
    for (int j = 0; j < HID; j++) {
        float s = sb2[j];
        #pragma unroll
        for (int k = 0; k < 32; k++) s += t1[k] * s2[k * HID + j];
        t2[j] = elu1f(s);
    }
    #pragma unroll
    for (int j = 0; j < 32; j++) {
        float s = sb3[j];
        #pragma unroll
        for (int k = 0; k < HID; k++) s += t2[k] * s3[k * 32 + j];
        out[b * 32 + j] = s;
    }
}

// ---------------- launch ----------------
extern "C" void kernel_launch(void* const* d_in, const int* in_sizes, int n_in,
                              void* d_out, int out_size) {
    const float* x     = (const float*)d_in[0];
    const int*   ei    = (const int*)  d_in[1];
    const int*   batch = (const int*)  d_in[2];
    const float* wl1   = (const float*)d_in[3];
    const float* bl1   = (const float*)d_in[4];
    const float* wr1   = (const float*)d_in[5];
    const float* br1   = (const float*)d_in[6];
    const float* att1  = (const float*)d_in[7];
    const float* bias1 = (const float*)d_in[8];
    const float* wl2   = (const float*)d_in[9];
    const float* bl2   = (const float*)d_in[10];
    const float* wr2   = (const float*)d_in[11];
    const float* br2   = (const float*)d_in[12];
    const float* att2  = (const float*)d_in[13];
    const float* bias2 = (const float*)d_in[14];
    const float* wm1   = (const float*)d_in[15];
    const float* bm1   = (const float*)d_in[16];
    const float* wm2   = (const float*)d_in[17];
    const float* bm2   = (const float*)d_in[18];
    const float* wm3   = (const float*)d_in[19];
    const float* bm3   = (const float*)d_in[20];
    const int* src = ei;
    const int* dst = ei + NEDGES;
    float* out = (float*)d_out;

    zero_kernel<<<2048, 256>>>();
    gemm1_kernel<<<(NNODES + 31) / 32, 256>>>(x, wl1, bl1, wr1, br1);
    int eb1 = (ETOT * HEADS + 255) / 256;
    edge1_logit_kernel<<<eb1, 256>>>(src, dst, att1);
    edge1_scatter_kernel<<<eb1, 256>>>(src, dst);
    elu1_kernel<<<(NNODES * HH + 255) / 256, 256>>>(bias1);
    gemm2_kernel<<<(NNODES + 31) / 32, 256>>>(wl2, bl2, wr2, br2);
    int eb2 = (ETOT + 255) / 256;
    edge2_logit_kernel<<<eb2, 256>>>(src, dst, att2);
    edge2_scatter_kernel<<<eb2, 256>>>(src, dst);
    pool_kernel<<<(NNODES + 255) / 256, 256>>>(batch, bias2);
    mlp_kernel<<<1, 256>>>(wm1, bm1, wm2, bm2, wm3, bm3, out);
}

// round 2
// speedup vs baseline: 2.4488x; 2.4488x over previous
#include <cuda_runtime.h>
#include <math.h>

#define NNODES 50000
#define NEDGES 1600000
#define ETOT   (NEDGES + NNODES)
#define INCH   64
#define HEADS  8
#define HID    16
#define HH     (HEADS*HID)   /* 128 */
#define NGRAPH 256
#define OUTC   32
#define NB     ((NNODES + 1023) / 1024)   /* scan blocks = 49 */

// ---------------- scratch ----------------
__device__ __align__(16) float g_xl1[NNODES*HH];
__device__ __align__(16) float g_xr1[NNODES*HH];
__device__ __align__(16) float g_out1[NNODES*HH];
__device__ __align__(16) float g_xl2[NNODES*HID];
__device__ __align__(16) float g_xr2[NNODES*HID];
__device__ __align__(16) float g_pool[NGRAPH*HID];
__device__ __align__(16) float g_cnt[NGRAPH];
// CSR (by destination)
__device__ int g_count[NNODES];
__device__ int g_rowstart[NNODES + 1];
__device__ int g_cursor[NNODES];
__device__ int g_blocksum[NB];
__device__ int g_blockoff[NB];
__device__ int g_csrsrc[ETOT];

__device__ __forceinline__ float elu1f(float v) { return v > 0.f ? v : expm1f(v); }
__device__ __forceinline__ float lrelu(float v) { return v > 0.f ? v : 0.2f * v; }

// ---------------- zero ----------------
__global__ void zero_kernel() {
    int stride = gridDim.x * blockDim.x;
    int i0 = blockIdx.x * blockDim.x + threadIdx.x;
    for (int i = i0; i < NNODES;     i += stride) g_count[i] = 0;
    for (int i = i0; i < NGRAPH*HID; i += stride) g_pool[i]  = 0.f;
    for (int i = i0; i < NGRAPH;     i += stride) g_cnt[i]   = 0.f;
}

// ---------------- CSR build ----------------
__global__ void hist_kernel(const int* __restrict__ dst) {
    int e = blockIdx.x * blockDim.x + threadIdx.x;
    if (e >= ETOT) return;
    int d = (e < NEDGES) ? dst[e] : (e - NEDGES);
    atomicAdd(&g_count[d], 1);
}

__global__ void scan1_kernel() {   // per-block sums (block = 1024)
    __shared__ int s;
    if (threadIdx.x == 0) s = 0;
    __syncthreads();
    int i = blockIdx.x * 1024 + threadIdx.x;
    int v = (i < NNODES) ? g_count[i] : 0;
    #pragma unroll
    for (int o = 16; o; o >>= 1) v += __shfl_xor_sync(0xffffffffu, v, o);
    if ((threadIdx.x & 31) == 0) atomicAdd(&s, v);
    __syncthreads();
    if (threadIdx.x == 0) g_blocksum[blockIdx.x] = s;
}

__global__ void scan2_kernel() {   // exclusive scan of 49 block sums
    if (threadIdx.x == 0) {
        int acc = 0;
        for (int b = 0; b < NB; b++) { g_blockoff[b] = acc; acc += g_blocksum[b]; }
    }
}

__global__ void scan3_kernel() {   // per-block exclusive scan + offsets
    __shared__ int warpsum[32];
    int i = blockIdx.x * 1024 + threadIdx.x;
    int lane = threadIdx.x & 31, wid = threadIdx.x >> 5;
    int v = (i < NNODES) ? g_count[i] : 0;
    int incl = v;
    #pragma unroll
    for (int o = 1; o < 32; o <<= 1) {
        int t = __shfl_up_sync(0xffffffffu, incl, o);
        if (lane >= o) incl += t;
    }
    if (lane == 31) warpsum[wid] = incl;
    __syncthreads();
    if (wid == 0) {
        int s = warpsum[lane];
        #pragma unroll
        for (int o = 1; o < 32; o <<= 1) {
            int t = __shfl_up_sync(0xffffffffu, s, o);
            if (lane >= o) s += t;
        }
        warpsum[lane] = s;
    }
    __syncthreads();
    int base = g_blockoff[blockIdx.x] + (wid ? warpsum[wid - 1] : 0);
    int excl = base + incl - v;
    if (i < NNODES) { g_rowstart[i] = excl; g_cursor[i] = excl; }
    if (i == NNODES - 1) g_rowstart[NNODES] = excl + v;
}

__global__ void fill_kernel(const int* __restrict__ src, const int* __restrict__ dst) {
    int e = blockIdx.x * blockDim.x + threadIdx.x;
    if (e >= ETOT) return;
    int s, d;
    if (e < NEDGES) { s = src[e]; d = dst[e]; } else { s = e - NEDGES; d = s; }
    int pos = atomicAdd(&g_cursor[d], 1);
    g_csrsrc[pos] = s;
}

// ---------------- conv1 node transforms ----------------
__global__ void gemm1_kernel(const float* __restrict__ x,
                             const float* __restrict__ wl, const float* __restrict__ bl,
                             const float* __restrict__ wr, const float* __restrict__ br) {
    __shared__ float xs[8][INCH];
    int tid = threadIdx.x;
    int c = tid & (HH - 1);
    const float* w = (tid < HH) ? wl : wr;
    float bias = (tid < HH) ? bl[c] : br[c];
    int node0 = blockIdx.x * 32;
    for (int base = 0; base < 32; base += 8) {
        int n0 = node0 + base;
        __syncthreads();
        for (int i = tid; i < 8 * INCH; i += 256) {
            int nn = i >> 6, kk = i & 63;
            int g = n0 + nn;
            xs[nn][kk] = (g < NNODES) ? x[g * INCH + kk] : 0.f;
        }
        __syncthreads();
        float acc[8];
        #pragma unroll
        for (int j = 0; j < 8; j++) acc[j] = bias;
        #pragma unroll 8
        for (int k = 0; k < INCH; k++) {
            float wv = __ldg(&w[k * HH + c]);
            #pragma unroll
            for (int j = 0; j < 8; j++) acc[j] += xs[j][k] * wv;
        }
        float* outp = (tid < HH) ? g_xl1 : g_xr1;
        #pragma unroll
        for (int j = 0; j < 8; j++) {
            int g = n0 + j;
            if (g < NNODES) outp[(size_t)g * HH + c] = acc[j];
        }
    }
}

// ---------------- conv1 fused edge pass: one warp per dst node ----------------
// lane = h*4 + c4  (head h = lane>>2, 4 channels per lane)
// Single pass: logit -> exp -> accumulate num & denom in registers; write
// elu(out/denom + bias1) once. No atomics, no a1/denom arrays.
__global__ void __launch_bounds__(256) edge1_fused_kernel(const float* __restrict__ att,
                                                          const float* __restrict__ bias) {
    int warp = (blockIdx.x * blockDim.x + threadIdx.x) >> 5;
    if (warp >= NNODES) return;
    int lane = threadIdx.x & 31;
    int d = warp;
    float4 xr = ((const float4*)(g_xr1 + (size_t)d * HH))[lane];
    float4 aw = __ldg(&((const float4*)att)[lane]);
    float4 acc = make_float4(0.f, 0.f, 0.f, 0.f);
    float den = 0.f;
    int beg = g_rowstart[d], end = g_rowstart[d + 1];
    int i = beg;
    for (; i + 1 < end; i += 2) {           // two independent gathers in flight
        int s0 = g_csrsrc[i], s1 = g_csrsrc[i + 1];
        float4 x0 = ((const float4*)(g_xl1 + (size_t)s0 * HH))[lane];
        float4 x1 = ((const float4*)(g_xl1 + (size_t)s1 * HH))[lane];
        float p0 = lrelu(x0.x + xr.x) * aw.x + lrelu(x0.y + xr.y) * aw.y
                 + lrelu(x0.z + xr.z) * aw.z + lrelu(x0.w + xr.w) * aw.w;
        float p1 = lrelu(x1.x + xr.x) * aw.x + lrelu(x1.y + xr.y) * aw.y
                 + lrelu(x1.z + xr.z) * aw.z + lrelu(x1.w + xr.w) * aw.w;
        p0 += __shfl_xor_sync(0xffffffffu, p0, 1);
        p0 += __shfl_xor_sync(0xffffffffu, p0, 2);
        p1 += __shfl_xor_sync(0xffffffffu, p1, 1);
        p1 += __shfl_xor_sync(0xffffffffu, p1, 2);
        float e0 = __expf(p0), e1 = __expf(p1);
        acc.x += e0 * x0.x + e1 * x1.x;
        acc.y += e0 * x0.y + e1 * x1.y;
        acc.z += e0 * x0.z + e1 * x1.z;
        acc.w += e0 * x0.w + e1 * x1.w;
        den += e0 + e1;
    }
    if (i < end) {
        int s0 = g_csrsrc[i];
        float4 x0 = ((const float4*)(g_xl1 + (size_t)s0 * HH))[lane];
        float p0 = lrelu(x0.x + xr.x) * aw.x + lrelu(x0.y + xr.y) * aw.y
                 + lrelu(x0.z + xr.z) * aw.z + lrelu(x0.w + xr.w) * aw.w;
        p0 += __shfl_xor_sync(0xffffffffu, p0, 1);
        p0 += __shfl_xor_sync(0xffffffffu, p0, 2);
        float e0 = __expf(p0);
        acc.x += e0 * x0.x; acc.y += e0 * x0.y; acc.z += e0 * x0.z; acc.w += e0 * x0.w;
        den += e0;
    }
    float inv = 1.f / (den + 1e-16f);
    float4 b = __ldg(&((const float4*)bias)[lane]);
    float4 o;
    o.x = elu1f(acc.x * inv + b.x);
    o.y = elu1f(acc.y * inv + b.y);
    o.z = elu1f(acc.z * inv + b.z);
    o.w = elu1f(acc.w * inv + b.w);
    ((float4*)(g_out1 + (size_t)d * HH))[lane] = o;
}

// ---------------- conv2 node transforms ----------------
__global__ void gemm2_kernel(const float* __restrict__ wl, const float* __restrict__ bl,
                             const float* __restrict__ wr, const float* __restrict__ br) {
    __shared__ float ws[HH][32];
    __shared__ float bs[32];
    __shared__ float xs[8][HH];
    int tid = threadIdx.x;
    for (int i = tid; i < HH * 32; i += 256) {
        int k = i >> 5, cc = i & 31;
        ws[k][cc] = (cc < HID) ? wl[k * HID + cc] : wr[k * HID + (cc - HID)];
    }
    if (tid < 32) bs[tid] = (tid < HID) ? bl[tid] : br[tid - HID];
    int col = tid & 31;
    int ln = tid >> 5;
    int node0 = blockIdx.x * 32;
    for (int base = 0; base < 32; base += 8) {
        int n0 = node0 + base;
        __syncthreads();
        for (int i = tid; i < 8 * HH; i += 256) {
            int nn = i >> 7, kk = i & 127;
            int g = n0 + nn;
            xs[nn][kk] = (g < NNODES) ? g_out1[(size_t)g * HH + kk] : 0.f;
        }
        __syncthreads();
        int g = n0 + ln;
        float acc = bs[col];
        #pragma unroll 8
        for (int k = 0; k < HH; k++) acc += xs[ln][k] * ws[k][col];
        if (g < NNODES) {
            if (col < HID) g_xl2[(size_t)g * HID + col] = acc;
            else           g_xr2[(size_t)g * HID + (col - HID)] = acc;
        }
    }
}

// ---------------- conv2 fused edge pass + bias2 + ELU + mean-pool scatter ----------------
// One warp per dst node; half-warps process alternating edges (c = lane&15).
__global__ void __launch_bounds__(256) edge2_fused_kernel(const float* __restrict__ att,
                                                          const float* __restrict__ bias,
                                                          const int* __restrict__ batch) {
    int warp = (blockIdx.x * blockDim.x + threadIdx.x) >> 5;
    if (warp >= NNODES) return;
    int lane = threadIdx.x & 31;
    int c = lane & 15;
    int sub = lane >> 4;
    int d = warp;
    float xr = g_xr2[(size_t)d * HID + c];
    float aw = __ldg(&att[c]);
    float acc = 0.f, den = 0.f;
    int beg = g_rowstart[d], end = g_rowstart[d + 1];
    int nit = (end - beg + 1) >> 1;
    for (int it = 0; it < nit; it++) {
        int idx = beg + 2 * it + sub;
        bool ok = idx < end;
        int s = ok ? g_csrsrc[idx] : 0;
        float xl = g_xl2[(size_t)s * HID + c];
        float p = lrelu(xl + xr) * aw;
        p += __shfl_xor_sync(0xffffffffu, p, 1);
        p += __shfl_xor_sync(0xffffffffu, p, 2);
        p += __shfl_xor_sync(0xffffffffu, p, 4);
        p += __shfl_xor_sync(0xffffffffu, p, 8);
        float ex = ok ? __expf(p) : 0.f;
        acc += ex * xl;
        den += ex;
    }
    acc += __shfl_xor_sync(0xffffffffu, acc, 16);
    den += __shfl_xor_sync(0xffffffffu, den, 16);
    if (sub == 0) {
        float o = elu1f(acc / (den + 1e-16f) + __ldg(&bias[c]));
        int b = batch[d];
        atomicAdd(&g_pool[b * HID + c], o);
        if (c == 0) atomicAdd(&g_cnt[b], 1.f);
    }
}

// ---------------- final MLP ----------------
__global__ void mlp_kernel(const float* __restrict__ w1, const float* __restrict__ b1,
                           const float* __restrict__ w2, const float* __restrict__ b2,
                           const float* __restrict__ w3, const float* __restrict__ b3,
                           float* __restrict__ out) {
    __shared__ float s1[HID * 32], sb1[32];
    __shared__ float s2[32 * HID], sb2[HID];
    __shared__ float s3[HID * 32], sb3[32];
    int tid = threadIdx.x;
    for (int i = tid; i < HID * 32; i += 256) s1[i] = w1[i];
    for (int i = tid; i < 32 * HID; i += 256) s2[i] = w2[i];
    for (int i = tid; i < HID * 32; i += 256) s3[i] = w3[i];
    if (tid < 32) { sb1[tid] = b1[tid]; sb3[tid] = b3[tid]; }
    if (tid < HID) sb2[tid] = b2[tid];
    __syncthreads();
    int b = tid;
    float cnt = fmaxf(g_cnt[b], 1.f);
    float h[HID];
    #pragma unroll
    for (int c = 0; c < HID; c++) h[c] = g_pool[b * HID + c] / cnt;
    float t1[32];
    #pragma unroll
    for (int j = 0; j < 32; j++) {
        float s = sb1[j];
        #pragma unroll
        for (int k = 0; k < HID; k++) s += h[k] * s1[k * 32 + j];
        t1[j] = elu1f(s);
    }
    float t2[HID];
    #pragma unroll
    for (int j = 0; j < HID; j++) {
        float s = sb2[j];
        #pragma unroll
        for (int k = 0; k < 32; k++) s += t1[k] * s2[k * HID + j];
        t2[j] = elu1f(s);
    }
    #pragma unroll
    for (int j = 0; j < 32; j++) {
        float s = sb3[j];
        #pragma unroll
        for (int k = 0; k < HID; k++) s += t2[k] * s3[k * 32 + j];
        out[b * 32 + j] = s;
    }
}

// ---------------- launch ----------------
extern "C" void kernel_launch(void* const* d_in, const int* in_sizes, int n_in,
                              void* d_out, int out_size) {
    const float* x     = (const float*)d_in[0];
    const int*   ei    = (const int*)  d_in[1];
    const int*   batch = (const int*)  d_in[2];
    const float* wl1   = (const float*)d_in[3];
    const float* bl1   = (const float*)d_in[4];
    const float* wr1   = (const float*)d_in[5];
    const float* br1   = (const float*)d_in[6];
    const float* att1  = (const float*)d_in[7];
    const float* bias1 = (const float*)d_in[8];
    const float* wl2   = (const float*)d_in[9];
    const float* bl2   = (const float*)d_in[10];
    const float* wr2   = (const float*)d_in[11];
    const float* br2   = (const float*)d_in[12];
    const float* att2  = (const float*)d_in[13];
    const float* bias2 = (const float*)d_in[14];
    const float* wm1   = (const float*)d_in[15];
    const float* bm1   = (const float*)d_in[16];
    const float* wm2   = (const float*)d_in[17];
    const float* bm2   = (const float*)d_in[18];
    const float* wm3   = (const float*)d_in[19];
    const float* bm3   = (const float*)d_in[20];
    const int* src = ei;
    const int* dst = ei + NEDGES;
    float* out = (float*)d_out;

    int ebl = (ETOT + 255) / 256;
    zero_kernel<<<512, 256>>>();
    hist_kernel<<<ebl, 256>>>(dst);
    scan1_kernel<<<NB, 1024>>>();
    scan2_kernel<<<1, 32>>>();
    scan3_kernel<<<NB, 1024>>>();
    fill_kernel<<<ebl, 256>>>(src, dst);
    gemm1_kernel<<<(NNODES + 31) / 32, 256>>>(x, wl1, bl1, wr1, br1);
    edge1_fused_kernel<<<(NNODES * 32 + 255) / 256, 256>>>(att1, bias1);
    gemm2_kernel<<<(NNODES + 31) / 32, 256>>>(wl2, bl2, wr2, br2);
    edge2_fused_kernel<<<(NNODES * 32 + 255) / 256, 256>>>(att2, bias2, batch);
    mlp_kernel<<<1, 256>>>(wm1, bm1, wm2, bm2, wm3, bm3, out);
}

// round 4
// speedup vs baseline: 2.6749x; 1.0923x over previous
#include <cuda_runtime.h>
#include <math.h>

#define NNODES 50000
#define NEDGES 1600000
#define ETOT   (NEDGES + NNODES)
#define INCH   64
#define HEADS  8
#define HID    16
#define HH     (HEADS*HID)   /* 128 */
#define NGRAPH 256
#define OUTC   32
#define NB     ((NNODES + 1023) / 1024)   /* 49 */
#define GG     ((NNODES + 31) / 32)       /* gemm1 blocks = 1563 */
#define GH     ((ETOT + 255) / 256)       /* hist blocks  = 6446 */

// ---------------- scratch ----------------
__device__ __align__(16) float g_xl1[NNODES*HH];
__device__ __align__(16) float g_xr1[NNODES*HH];
__device__ __align__(16) float g_out1[NNODES*HH];
__device__ __align__(16) float g_xl2[NNODES*HID];
__device__ __align__(16) float g_xr2[NNODES*HID];
__device__ __align__(16) float g_pool[NGRAPH*HID];
__device__ __align__(16) float g_cnt[NGRAPH];
__device__ int g_count[NNODES];
__device__ int g_rowstart[NNODES + 1];
__device__ int g_cursor[NNODES];
__device__ int g_blocksum[NB];
__device__ int g_blockoff[NB];
__device__ int g_csrsrc[ETOT];

__device__ __forceinline__ float elu1f(float v) { return v > 0.f ? v : expm1f(v); }
__device__ __forceinline__ float lrelu(float v) { return fmaxf(v, 0.2f * v); }

// ---------------- zero g_count ----------------
__global__ void zero_kernel() {
    int i = blockIdx.x * blockDim.x + threadIdx.x;
    if (i < NNODES) g_count[i] = 0;
}

// ---------------- fused: gemm1 (first GG blocks) || hist (rest) ----------------
__global__ void __launch_bounds__(256) fusedA_kernel(
        const float* __restrict__ x,
        const float* __restrict__ wl, const float* __restrict__ bl,
        const float* __restrict__ wr, const float* __restrict__ br,
        const int* __restrict__ dst) {
    if (blockIdx.x >= GG) {
        int e = (blockIdx.x - GG) * 256 + threadIdx.x;
        if (e < ETOT) {
            int d = (e < NEDGES) ? dst[e] : (e - NEDGES);
            atomicAdd(&g_count[d], 1);
        }
        return;
    }
    __shared__ __align__(16) float xs[8][INCH];
    int tid = threadIdx.x;
    int c = tid & (HH - 1);
    const float* w = (tid < HH) ? wl : wr;
    float bias = (tid < HH) ? bl[c] : br[c];
    float wreg[INCH];
    #pragma unroll
    for (int k = 0; k < INCH; k++) wreg[k] = __ldg(&w[k * HH + c]);
    float* outp = (tid < HH) ? g_xl1 : g_xr1;
    int node0 = blockIdx.x * 32;
    for (int base = 0; base < 32; base += 8) {
        int n0 = node0 + base;
        __syncthreads();
        if (tid < 128) {
            int nn = tid >> 4, k4 = tid & 15;
            int g = n0 + nn;
            float4 v = (g < NNODES) ? ((const float4*)(x + (size_t)g * INCH))[k4]
                                    : make_float4(0.f, 0.f, 0.f, 0.f);
            ((float4*)&xs[nn][0])[k4] = v;
        }
        __syncthreads();
        float acc[8];
        #pragma unroll
        for (int j = 0; j < 8; j++) acc[j] = bias;
        #pragma unroll
        for (int k4 = 0; k4 < 16; k4++) {
            #pragma unroll
            for (int j = 0; j < 8; j++) {
                float4 xv = ((const float4*)&xs[j][0])[k4];
                acc[j] = fmaf(xv.x, wreg[4 * k4 + 0],
                         fmaf(xv.y, wreg[4 * k4 + 1],
                         fmaf(xv.z, wreg[4 * k4 + 2],
                         fmaf(xv.w, wreg[4 * k4 + 3], acc[j]))));
            }
        }
        #pragma unroll
        for (int j = 0; j < 8; j++) {
            int g = n0 + j;
            if (g < NNODES) outp[(size_t)g * HH + c] = acc[j];
        }
    }
}

// ---------------- scan chain ----------------
__global__ void scan1_kernel() {
    __shared__ int s;
    if (threadIdx.x == 0) s = 0;
    __syncthreads();
    int i = blockIdx.x * 1024 + threadIdx.x;
    int v = (i < NNODES) ? g_count[i] : 0;
    #pragma unroll
    for (int o = 16; o; o >>= 1) v += __shfl_xor_sync(0xffffffffu, v, o);
    if ((threadIdx.x & 31) == 0) atomicAdd(&s, v);
    __syncthreads();
    if (threadIdx.x == 0) g_blocksum[blockIdx.x] = s;
}

__global__ void scan2_kernel() {    // parallel scan of 49 sums + zero pool/cnt
    __shared__ int sv[64];
    int t = threadIdx.x;            // 256
    if (t < 64) sv[t] = (t < NB) ? g_blocksum[t] : 0;
    __syncthreads();
    #pragma unroll
    for (int o = 1; o < 64; o <<= 1) {
        int v = 0;
        if (t < 64) { v = sv[t]; if (t >= o) v += sv[t - o]; }
        __syncthreads();
        if (t < 64) sv[t] = v;
        __syncthreads();
    }
    if (t < NB) g_blockoff[t] = t ? sv[t - 1] : 0;
    for (int i = t; i < NGRAPH * HID; i += 256) g_pool[i] = 0.f;
    for (int i = t; i < NGRAPH; i += 256) g_cnt[i] = 0.f;
}

__global__ void scan3_kernel() {
    __shared__ int warpsum[32];
    int i = blockIdx.x * 1024 + threadIdx.x;
    int lane = threadIdx.x & 31, wid = threadIdx.x >> 5;
    int v = (i < NNODES) ? g_count[i] : 0;
    int incl = v;
    #pragma unroll
    for (int o = 1; o < 32; o <<= 1) {
        int t = __shfl_up_sync(0xffffffffu, incl, o);
        if (lane >= o) incl += t;
    }
    if (lane == 31) warpsum[wid] = incl;
    __syncthreads();
    if (wid == 0) {
        int s = warpsum[lane];
        #pragma unroll
        for (int o = 1; o < 32; o <<= 1) {
            int t = __shfl_up_sync(0xffffffffu, s, o);
            if (lane >= o) s += t;
        }
        warpsum[lane] = s;
    }
    __syncthreads();
    int base = g_blockoff[blockIdx.x] + (wid ? warpsum[wid - 1] : 0);
    int excl = base + incl - v;
    if (i < NNODES) { g_rowstart[i] = excl; g_cursor[i] = excl; }
    if (i == NNODES - 1) g_rowstart[NNODES] = excl + v;
}

__global__ void fill_kernel(const int* __restrict__ src, const int* __restrict__ dst) {
    int e = blockIdx.x * blockDim.x + threadIdx.x;
    if (e >= ETOT) return;
    int s, d;
    if (e < NEDGES) { s = src[e]; d = dst[e]; } else { s = e - NEDGES; d = s; }
    int pos = atomicAdd(&g_cursor[d], 1);
    g_csrsrc[pos] = s;
}

// ---------------- conv1 fused edge pass: one warp per dst node, 4-deep pipeline ----------------
__device__ __forceinline__ float edge1_exp(float4 xv, float4 xr, float4 aw) {
    float p = lrelu(xv.x + xr.x) * aw.x + lrelu(xv.y + xr.y) * aw.y
            + lrelu(xv.z + xr.z) * aw.z + lrelu(xv.w + xr.w) * aw.w;
    p += __shfl_xor_sync(0xffffffffu, p, 1);
    p += __shfl_xor_sync(0xffffffffu, p, 2);
    return __expf(p);
}

__global__ void __launch_bounds__(256) edge1_fused_kernel(const float* __restrict__ att,
                                                          const float* __restrict__ bias) {
    int warp = (blockIdx.x * blockDim.x + threadIdx.x) >> 5;
    if (warp >= NNODES) return;
    int lane = threadIdx.x & 31;
    int d = warp;
    float4 xr = ((const float4*)(g_xr1 + (size_t)d * HH))[lane];
    float4 aw = __ldg(&((const float4*)att)[lane]);
    float4 acc = make_float4(0.f, 0.f, 0.f, 0.f);
    float den = 0.f;
    int beg = g_rowstart[d], end = g_rowstart[d + 1];
    int i = beg;
    for (; i + 3 < end; i += 4) {   // warp-uniform trip count
        int s0 = g_csrsrc[i], s1 = g_csrsrc[i + 1], s2 = g_csrsrc[i + 2], s3 = g_csrsrc[i + 3];
        float4 x0 = ((const float4*)(g_xl1 + (size_t)s0 * HH))[lane];
        float4 x1 = ((const float4*)(g_xl1 + (size_t)s1 * HH))[lane];
        float4 x2 = ((const float4*)(g_xl1 + (size_t)s2 * HH))[lane];
        float4 x3 = ((const float4*)(g_xl1 + (size_t)s3 * HH))[lane];
        float e0 = edge1_exp(x0, xr, aw);
        float e1 = edge1_exp(x1, xr, aw);
        float e2 = edge1_exp(x2, xr, aw);
        float e3 = edge1_exp(x3, xr, aw);
        acc.x += e0 * x0.x + e1 * x1.x + e2 * x2.x + e3 * x3.x;
        acc.y += e0 * x0.y + e1 * x1.y + e2 * x2.y + e3 * x3.y;
        acc.z += e0 * x0.z + e1 * x1.z + e2 * x2.z + e3 * x3.z;
        acc.w += e0 * x0.w + e1 * x1.w + e2 * x2.w + e3 * x3.w;
        den += (e0 + e1) + (e2 + e3);
    }
    for (; i < end; i++) {          // warp-uniform
        int s0 = g_csrsrc[i];
        float4 x0 = ((const float4*)(g_xl1 + (size_t)s0 * HH))[lane];
        float e0 = edge1_exp(x0, xr, aw);
        acc.x += e0 * x0.x; acc.y += e0 * x0.y; acc.z += e0 * x0.z; acc.w += e0 * x0.w;
        den += e0;
    }
    float inv = 1.f / (den + 1e-16f);
    float4 b = __ldg(&((const float4*)bias)[lane]);
    float4 o;
    o.x = elu1f(fmaf(acc.x, inv, b.x));
    o.y = elu1f(fmaf(acc.y, inv, b.y));
    o.z = elu1f(fmaf(acc.z, inv, b.z));
    o.w = elu1f(fmaf(acc.w, inv, b.w));
    ((float4*)(g_out1 + (size_t)d * HH))[lane] = o;
}

// ---------------- conv2 node transforms ----------------
__global__ void __launch_bounds__(256) gemm2_kernel(
        const float* __restrict__ wl, const float* __restrict__ bl,
        const float* __restrict__ wr, const float* __restrict__ br) {
    __shared__ float ws[HH][32];
    __shared__ float bs[32];
    __shared__ __align__(16) float xs[8][HH];
    int tid = threadIdx.x;
    for (int i = tid; i < HH * 32; i += 256) {
        int k = i >> 5, cc = i & 31;
        ws[k][cc] = (cc < HID) ? wl[k * HID + cc] : wr[k * HID + (cc - HID)];
    }
    if (tid < 32) bs[tid] = (tid < HID) ? bl[tid] : br[tid - HID];
    int col = tid & 31;
    int ln = tid >> 5;
    int node0 = blockIdx.x * 32;
    for (int base = 0; base < 32; base += 8) {
        int n0 = node0 + base;
        __syncthreads();
        {
            int nn = tid >> 5, k4 = tid & 31;
            int g = n0 + nn;
            float4 v = (g < NNODES) ? ((const float4*)(g_out1 + (size_t)g * HH))[k4]
                                    : make_float4(0.f, 0.f, 0.f, 0.f);
            ((float4*)&xs[nn][0])[k4] = v;
        }
        __syncthreads();
        int g = n0 + ln;
        float acc = bs[col];
        #pragma unroll
        for (int k4 = 0; k4 < 32; k4++) {
            float4 xv = ((const float4*)&xs[ln][0])[k4];
            acc = fmaf(xv.x, ws[4 * k4 + 0][col],
                  fmaf(xv.y, ws[4 * k4 + 1][col],
                  fmaf(xv.z, ws[4 * k4 + 2][col],
                  fmaf(xv.w, ws[4 * k4 + 3][col], acc))));
        }
        if (g < NNODES) {
            if (col < HID) g_xl2[(size_t)g * HID + col] = acc;
            else           g_xr2[(size_t)g * HID + (col - HID)] = acc;
        }
    }
}

// ---------------- conv2 fused edge pass + bias2 + ELU + mean-pool ----------------
// Half-warps process alternating edges; ALL loops have warp-uniform trip counts
// (inactive lanes masked via ok predicate) so every __shfl_xor is convergent.
__global__ void __launch_bounds__(256) edge2_fused_kernel(const float* __restrict__ att,
                                                          const float* __restrict__ bias,
                                                          const int* __restrict__ batch) {
    int warp = (blockIdx.x * blockDim.x + threadIdx.x) >> 5;
    if (warp >= NNODES) return;
    int lane = threadIdx.x & 31;
    int c = lane & 15;
    int sub = lane >> 4;
    int d = warp;
    float xr = g_xr2[(size_t)d * HID + c];
    float aw = __ldg(&att[c]);
    float acc = 0.f, den = 0.f;
    int beg = g_rowstart[d], end = g_rowstart[d + 1];
    int i = beg;
    for (; i + 3 < end; i += 4) {   // uniform: processes 4 edges, both halves fully active
        int idx0 = i + sub, idx1 = i + 2 + sub;
        int s0 = g_csrsrc[idx0], s1 = g_csrsrc[idx1];
        float xl0 = g_xl2[(size_t)s0 * HID + c];
        float xl1 = g_xl2[(size_t)s1 * HID + c];
        float p0 = lrelu(xl0 + xr) * aw;
        float p1 = lrelu(xl1 + xr) * aw;
        p0 += __shfl_xor_sync(0xffffffffu, p0, 1);
        p1 += __shfl_xor_sync(0xffffffffu, p1, 1);
        p0 += __shfl_xor_sync(0xffffffffu, p0, 2);
        p1 += __shfl_xor_sync(0xffffffffu, p1, 2);
        p0 += __shfl_xor_sync(0xffffffffu, p0, 4);
        p1 += __shfl_xor_sync(0xffffffffu, p1, 4);
        p0 += __shfl_xor_sync(0xffffffffu, p0, 8);
        p1 += __shfl_xor_sync(0xffffffffu, p1, 8);
        float e0 = __expf(p0), e1 = __expf(p1);
        acc += e0 * xl0 + e1 * xl1;
        den += e0 + e1;
    }
    {   // uniform tail: rem in 0..3, nit = ceil(rem/2), all lanes iterate nit times
        int rem = end - i;
        int nit = (rem + 1) >> 1;
        for (int it = 0; it < nit; it++) {
            int idx = i + 2 * it + sub;
            bool ok = idx < end;
            int s = ok ? g_csrsrc[idx] : 0;
            float xl = g_xl2[(size_t)s * HID + c];
            float p = lrelu(xl + xr) * aw;
            p += __shfl_xor_sync(0xffffffffu, p, 1);
            p += __shfl_xor_sync(0xffffffffu, p, 2);
            p += __shfl_xor_sync(0xffffffffu, p, 4);
            p += __shfl_xor_sync(0xffffffffu, p, 8);
            float ex = ok ? __expf(p) : 0.f;
            acc += ex * xl;
            den += ex;
        }
    }
    acc += __shfl_xor_sync(0xffffffffu, acc, 16);
    den += __shfl_xor_sync(0xffffffffu, den, 16);
    if (sub == 0) {
        float o = elu1f(acc / (den + 1e-16f) + __ldg(&bias[c]));
        int b = batch[d];
        atomicAdd(&g_pool[b * HID + c], o);
        if (c == 0) atomicAdd(&g_cnt[b], 1.f);
    }
}

// ---------------- final MLP ----------------
__global__ void mlp_kernel(const float* __restrict__ w1, const float* __restrict__ b1,
                           const float* __restrict__ w2, const float* __restrict__ b2,
                           const float* __restrict__ w3, const float* __restrict__ b3,
                           float* __restrict__ out) {
    __shared__ float s1[HID * 32], sb1[32];
    __shared__ float s2[32 * HID], sb2[HID];
    __shared__ float s3[HID * 32], sb3[32];
    int tid = threadIdx.x;
    for (int i = tid; i < HID * 32; i += 256) s1[i] = w1[i];
    for (int i = tid; i < 32 * HID; i += 256) s2[i] = w2[i];
    for (int i = tid; i < HID * 32; i += 256) s3[i] = w3[i];
    if (tid < 32) { sb1[tid] = b1[tid]; sb3[tid] = b3[tid]; }
    if (tid < HID) sb2[tid] = b2[tid];
    __syncthreads();
    int b = tid;
    float cnt = fmaxf(g_cnt[b], 1.f);
    float h[HID];
    #pragma unroll
    for (int c = 0; c < HID; c++) h[c] = g_pool[b * HID + c] / cnt;
    float t1[32];
    #pragma unroll
    for (int j = 0; j < 32; j++) {
        float s = sb1[j];
        #pragma unroll
        for (int k = 0; k < HID; k++) s += h[k] * s1[k * 32 + j];
        t1[j] = elu1f(s);
    }
    float t2[HID];
    #pragma unroll
    for (int j = 0; j < HID; j++) {
        float s = sb2[j];
        #pragma unroll
        for (int k = 0; k < 32; k++) s += t1[k] * s2[k * HID + j];
        t2[j] = elu1f(s);
    }
    #pragma unroll
    for (int j = 0; j < 32; j++) {
        float s = sb3[j];
        #pragma unroll
        for (int k = 0; k < HID; k++) s += t2[k] * s3[k * 32 + j];
        out[b * 32 + j] = s;
    }
}

// ---------------- launch ----------------
extern "C" void kernel_launch(void* const* d_in, const int* in_sizes, int n_in,
                              void* d_out, int out_size) {
    const float* x     = (const float*)d_in[0];
    const int*   ei    = (const int*)  d_in[1];
    const int*   batch = (const int*)  d_in[2];
    const float* wl1   = (const float*)d_in[3];
    const float* bl1   = (const float*)d_in[4];
    const float* wr1   = (const float*)d_in[5];
    const float* br1   = (const float*)d_in[6];
    const float* att1  = (const float*)d_in[7];
    const float* bias1 = (const float*)d_in[8];
    const float* wl2   = (const float*)d_in[9];
    const float* bl2   = (const float*)d_in[10];
    const float* wr2   = (const float*)d_in[11];
    const float* br2   = (const float*)d_in[12];
    const float* att2  = (const float*)d_in[13];
    const float* bias2 = (const float*)d_in[14];
    const float* wm1   = (const float*)d_in[15];
    const float* bm1   = (const float*)d_in[16];
    const float* wm2   = (const float*)d_in[17];
    const float* bm2   = (const float*)d_in[18];
    const float* wm3   = (const float*)d_in[19];
    const float* bm3   = (const float*)d_in[20];
    const int* src = ei;
    const int* dst = ei + NEDGES;
    float* out = (float*)d_out;

    zero_kernel<<<(NNODES + 511) / 512, 512>>>();
    fusedA_kernel<<<GG + GH, 256>>>(x, wl1, bl1, wr1, br1, dst);
    scan1_kernel<<<NB, 1024>>>();
    scan2_kernel<<<1, 256>>>();
    scan3_kernel<<<NB, 1024>>>();
    fill_kernel<<<(ETOT + 255) / 256, 256>>>(src, dst);
    edge1_fused_kernel<<<(NNODES * 32 + 255) / 256, 256>>>(att1, bias1);
    gemm2_kernel<<<(NNODES + 31) / 32, 256>>>(wl2, bl2, wr2, br2);
    edge2_fused_kernel<<<(NNODES * 32 + 255) / 256, 256>>>(att2, bias2, batch);
    mlp_kernel<<<1, 256>>>(wm1, bm1, wm2, bm2, wm3, bm3, out);
}